// round 2
// baseline (speedup 1.0000x reference)
#include <cuda_runtime.h>
#include <math.h>

// Problem constants
#define Hn    81
#define G3    243          // 3*H
#define RPAD  244          // rows padded to even (122 pairs)
#define NPAIR 122
#define Fn    128
#define Tn    1024
#define Bn    512
#define BPC   4            // batches per CTA
#define NCTA  128          // 512 / 4
#define NTHR  128          // recurrence threads
#define NTHR2 256          // gemm threads
#define TT    64           // timesteps per gemm CTA

// =====================================================================
// Device scratch
// =====================================================================
// XG[t][ctab][r(244)][b(4)] : x @ W_ih^T + b_ih, padded to 244 rows.
// 1024 * 128 * 244 * 4 floats = 512 MB.
__device__ float4 g_xg[Tn * NCTA * RPAD];
// per-batch post-GRU fc output (silu(h @ fc_w^T + fc_b)) [512][8]
__device__ float g_h8[Bn * 8];

// ---------- packed f32x2 helpers ----------
static __device__ __forceinline__ unsigned long long dup2(float x) {
    unsigned long long r;
    asm("mov.b64 %0, {%1, %1};" : "=l"(r) : "f"(x));
    return r;
}
static __device__ __forceinline__ void ffma2(unsigned long long &d,
                                             unsigned long long a,
                                             unsigned long long b) {
    asm("fma.rn.f32x2 %0, %1, %2, %0;" : "+l"(d) : "l"(a), "l"(b));
}
static __device__ __forceinline__ float2 unpk(unsigned long long v) {
    float lo, hi;
    asm("mov.b64 {%0, %1}, %2;" : "=f"(lo), "=f"(hi) : "l"(v));
    return make_float2(lo, hi);
}

// ---------- fast activations ----------
static __device__ __forceinline__ float sigm(float x) {
    x = fminf(fmaxf(x, -30.f), 30.f);
    return __fdividef(1.f, 1.f + __expf(-x));
}
static __device__ __forceinline__ float tanh_f(float x) {
    x = fminf(fmaxf(x, -20.f), 20.f);
    float e = __expf(-2.f * x);
    return __fdividef(1.f - e, 1.f + e);
}

// =====================================================================
// Kernel 1: XG precompute GEMM.
// grid (128 b-groups, 16 t-chunks) x 256 threads.
// Warps 0-3 handle even local t, warps 4-7 odd local t (2 warps/SMSP).
// =====================================================================
#define OFF2_WIH 0
#define SZ2_WIH  (Fn*NPAIR*8)              // 124928
#define OFF2_XS  (OFF2_WIH + SZ2_WIH)
#define SZ2_XS   (4*Fn*16)                 // 8192: [group*2 + buf][f] float4
#define SMEM2_BYTES (OFF2_XS + SZ2_XS)     // 133120

__global__ void __launch_bounds__(NTHR2, 1) xg_gemm(
    const float* __restrict__ x,     // [B,1,T,F]
    const float* __restrict__ W_ih,  // [3H,F]
    const float* __restrict__ b_ih)  // [3H]
{
    extern __shared__ char sm[];
    float2* wih2 = (float2*)(sm + OFF2_WIH);
    float*  xs_f = (float*)(sm + OFF2_XS);
    float4* xs4  = (float4*)(sm + OFF2_XS);

    const int tid   = threadIdx.x;
    const int group = tid >> 7;          // 0 or 1
    const int ltid  = tid & 127;
    const int ctab  = blockIdx.x;
    const int b0    = ctab * BPC;
    const int tbase = blockIdx.y * TT;

    // transpose + row-pair W_ih into SMEM
    for (int idx = tid; idx < RPAD * Fn; idx += NTHR2) {
        int k = idx & (Fn - 1);
        int r = idx >> 7;
        float v = (r < G3) ? W_ih[r * Fn + k] : 0.f;
        ((float*)wih2)[(k * NPAIR + (r >> 1)) * 2 + (r & 1)] = v;
    }
    __syncthreads();

    const int g = ltid;   // row-pair index, active for g < 122
    float bi0 = 0.f, bi1 = 0.f;
    if (g < NPAIR) {
        bi0 = b_ih[2 * g];
        bi1 = (2 * g + 1 < G3) ? b_ih[2 * g + 1] : 0.f;
    }

    for (int i = 0; i < TT / 2; i++) {
        const int t = tbase + 2 * i + group;
        const int buf = group * 2 + (i & 1);

        // stage x_t for this group's timestep: thread ltid = feature f
        {
            const float* xb = x + (long)t * Fn + ltid;
            float p0 = xb[(long)(b0 + 0) * Tn * Fn];
            float p1 = xb[(long)(b0 + 1) * Tn * Fn];
            float p2 = xb[(long)(b0 + 2) * Tn * Fn];
            float p3 = xb[(long)(b0 + 3) * Tn * Fn];
            xs4[buf * Fn + ltid] = make_float4(p0, p1, p2, p3);
        }
        __syncthreads();

        if (g < NPAIR) {
            unsigned long long a00 = 0, a01 = 0, a10 = 0, a11 = 0;
            const float2* wp = wih2 + g;
            const ulonglong2* xp = (const ulonglong2*)(xs_f + buf * (Fn * 4));
            #pragma unroll 16
            for (int k = 0; k < Fn; k++) {
                float2 w = wp[k * NPAIR];
                ulonglong2 xv = xp[k];
                unsigned long long w0 = dup2(w.x), w1 = dup2(w.y);
                ffma2(a00, w0, xv.x); ffma2(a01, w0, xv.y);
                ffma2(a10, w1, xv.x); ffma2(a11, w1, xv.y);
            }
            float2 u0 = unpk(a00), u1 = unpk(a01), u2 = unpk(a10), u3 = unpk(a11);
            float4* outp = g_xg + (long)(t * NCTA + ctab) * RPAD;
            outp[2 * g]     = make_float4(u0.x + bi0, u0.y + bi0, u1.x + bi0, u1.y + bi0);
            outp[2 * g + 1] = make_float4(u2.x + bi1, u2.y + bi1, u3.x + bi1, u3.y + bi1);
        }
    }
}

// =====================================================================
// Kernel 2: recurrence. 128 CTAs x 4 batches x 128 threads.
// Per step: hg = h @ W_hh^T (K=81) + gate combine; xg streamed from g_xg.
// =====================================================================
#define OFF_WHH 0
#define SZ_WHH  (Hn*NPAIR*8)               // 79056
#define OFF_XG  (OFF_WHH + SZ_WHH)
#define SZ_XG   (2*RPAD*16)                // 7808 double-buffered
#define OFF_HS  (OFF_XG + SZ_XG)
#define SZ_HS   (84*16)                    // 1344
#define OFF_HG  (OFF_HS + SZ_HS)
#define SZ_HG   (RPAD*16)                  // 3904
#define OFF_BHH (OFF_HG + SZ_HG)
#define SZ_BHH  (RPAD*4)                   // 976
#define SMEMR_BYTES (OFF_BHH + SZ_BHH)     // ~93KB

__global__ void __launch_bounds__(NTHR, 1) gru_rec(
    const float* __restrict__ W_hh,  // [3H,H]
    const float* __restrict__ b_hh,  // [3H]
    const float* __restrict__ fc_w,  // [8,H]
    const float* __restrict__ fc_b)  // [8]
{
    extern __shared__ char sm[];
    float2* whh2 = (float2*)(sm + OFF_WHH);
    float*  xg_f = (float*)(sm + OFF_XG);
    float4* xg4  = (float4*)(sm + OFF_XG);
    float*  hs_f = (float*)(sm + OFF_HS);
    float*  hg_f = (float*)(sm + OFF_HG);
    float4* hg4  = (float4*)(sm + OFF_HG);
    float*  bhh  = (float*)(sm + OFF_BHH);

    const int tid  = threadIdx.x;
    const int ctab = blockIdx.x;

    // init: W_hh transpose, biases, h=0, xg(t=0)
    for (int idx = tid; idx < RPAD * Hn; idx += NTHR) {
        int k = idx % Hn;
        int r = idx / Hn;
        float v = (r < G3) ? W_hh[r * Hn + k] : 0.f;
        ((float*)whh2)[(k * NPAIR + (r >> 1)) * 2 + (r & 1)] = v;
    }
    for (int idx = tid; idx < RPAD; idx += NTHR)
        bhh[idx] = (idx < G3) ? b_hh[idx] : 0.f;
    for (int idx = tid; idx < 84 * 4; idx += NTHR) hs_f[idx] = 0.f;
    {
        const float4* src = g_xg + (long)ctab * RPAD;   // t = 0
        xg4[tid] = src[tid];
        if (tid < RPAD - NTHR) xg4[NTHR + tid] = src[NTHR + tid];
    }
    __syncthreads();

    const int g = tid;  // row pair

    for (int t = 0; t < Tn; t++) {
        const int cur = t & 1, nxt = cur ^ 1;

        // prefetch xg(t+1) from gmem (coalesced float4)
        float4 q0 = make_float4(0.f, 0.f, 0.f, 0.f);
        float4 q1 = q0;
        const bool pf = (t + 1 < Tn);
        if (pf) {
            const float4* src = g_xg + (long)((t + 1) * NCTA + ctab) * RPAD;
            q0 = src[tid];
            if (tid < RPAD - NTHR) q1 = src[NTHR + tid];
        }

        if (g < NPAIR) {
            // hg = h @ W_hh^T (2 rows x 4 batches, f32x2)
            unsigned long long a00 = 0, a01 = 0, a10 = 0, a11 = 0;
            const float2* wq = whh2 + g;
            const ulonglong2* hp = (const ulonglong2*)hs_f;
            #pragma unroll 16
            for (int k = 0; k < Hn; k++) {
                float2 w = wq[k * NPAIR];
                ulonglong2 hv = hp[k];
                unsigned long long w0 = dup2(w.x), w1 = dup2(w.y);
                ffma2(a00, w0, hv.x); ffma2(a01, w0, hv.y);
                ffma2(a10, w1, hv.x); ffma2(a11, w1, hv.y);
            }
            float bh0 = bhh[2 * g], bh1 = bhh[2 * g + 1];
            float2 u0 = unpk(a00), u1 = unpk(a01), u2 = unpk(a10), u3 = unpk(a11);
            hg4[2 * g]     = make_float4(u0.x + bh0, u0.y + bh0, u1.x + bh0, u1.y + bh0);
            hg4[2 * g + 1] = make_float4(u2.x + bh1, u2.y + bh1, u3.x + bh1, u3.y + bh1);
        }

        // stash prefetched xg(t+1) (buffer not read this step)
        if (pf) {
            xg4[nxt * RPAD + tid] = q0;
            if (tid < RPAD - NTHR) xg4[nxt * RPAD + NTHR + tid] = q1;
        }

        __syncthreads();

        // gate combine: 81 hidden x 4 batches
        const float* xgc = xg_f + cur * (RPAD * 4);
        for (int it = tid; it < Hn * 4; it += NTHR) {
            float xr = xgc[it],              hr = hg_f[it];
            float xz = xgc[Hn * 4 + it],     hz = hg_f[Hn * 4 + it];
            float xn = xgc[2 * Hn * 4 + it], hn = hg_f[2 * Hn * 4 + it];
            float r = sigm(xr + hr);
            float z = sigm(xz + hz);
            float n = tanh_f(xn + r * hn);
            float hold = hs_f[it];
            hs_f[it] = (1.f - z) * n + z * hold;
        }
        __syncthreads();
    }

    // head stage 1: out8 = silu(h_last @ fc_w^T + fc_b)
    if (tid < 32) {
        int b = tid >> 3, f = tid & 7;
        float a = fc_b[f];
        #pragma unroll 27
        for (int j = 0; j < Hn; j++) a += hs_f[j * 4 + b] * fc_w[f * Hn + j];
        a = a * sigm(a);
        g_h8[(ctab * BPC + b) * 8 + f] = a;
    }
}

// =====================================================================
// Kernel 3: BN(8) -> fc1 -> silu -> BN(4) -> fc2. One CTA, 512 threads.
// =====================================================================
__global__ void __launch_bounds__(Bn) head_kernel(
    const float* __restrict__ g1, const float* __restrict__ beta1,
    const float* __restrict__ fc1_w, const float* __restrict__ fc1_b,
    const float* __restrict__ g2, const float* __restrict__ beta2,
    const float* __restrict__ fc2_w, const float* __restrict__ fc2_b,
    float* __restrict__ out)
{
    __shared__ float s8[Bn * 8];
    __shared__ float s4[Bn * 4];
    __shared__ float mu1[8], iv1[8], mu2[4], iv2[4];
    const int tid = threadIdx.x;

    for (int i = tid; i < Bn * 8; i += Bn) s8[i] = g_h8[i];
    __syncthreads();

    if (tid < 8) {
        float s = 0.f, ss = 0.f;
        for (int b = 0; b < Bn; b++) { float v = s8[b * 8 + tid]; s += v; ss += v * v; }
        float m = s * (1.f / Bn);
        float var = ss * (1.f / Bn) - m * m;   // biased variance
        mu1[tid] = m;
        iv1[tid] = rsqrtf(var + 1e-5f);
    }
    __syncthreads();

    {
        int b = tid;
        float y[8];
        #pragma unroll
        for (int f = 0; f < 8; f++)
            y[f] = (s8[b * 8 + f] - mu1[f]) * iv1[f] * g1[f] + beta1[f];
        #pragma unroll
        for (int o = 0; o < 4; o++) {
            float a = fc1_b[o];
            #pragma unroll
            for (int f = 0; f < 8; f++) a += y[f] * fc1_w[o * 8 + f];
            a = a * sigm(a);
            s4[b * 4 + o] = a;
        }
    }
    __syncthreads();

    if (tid < 4) {
        float s = 0.f, ss = 0.f;
        for (int b = 0; b < Bn; b++) { float v = s4[b * 4 + tid]; s += v; ss += v * v; }
        float m = s * (1.f / Bn);
        float var = ss * (1.f / Bn) - m * m;
        mu2[tid] = m;
        iv2[tid] = rsqrtf(var + 1e-5f);
    }
    __syncthreads();

    {
        int b = tid;
        float a = fc2_b[0];
        #pragma unroll
        for (int o = 0; o < 4; o++)
            a += ((s4[b * 4 + o] - mu2[o]) * iv2[o] * g2[o] + beta2[o]) * fc2_w[o];
        out[b] = a;
    }
}

// =====================================================================
extern "C" void kernel_launch(void* const* d_in, const int* in_sizes, int n_in,
                              void* d_out, int out_size) {
    const float* x     = (const float*)d_in[0];
    const float* W_ih  = (const float*)d_in[1];
    const float* W_hh  = (const float*)d_in[2];
    const float* b_ih  = (const float*)d_in[3];
    const float* b_hh  = (const float*)d_in[4];
    const float* fc_w  = (const float*)d_in[5];
    const float* fc_b  = (const float*)d_in[6];
    const float* g1    = (const float*)d_in[7];
    const float* beta1 = (const float*)d_in[8];
    const float* fc1_w = (const float*)d_in[9];
    const float* fc1_b = (const float*)d_in[10];
    const float* g2    = (const float*)d_in[11];
    const float* beta2 = (const float*)d_in[12];
    const float* fc2_w = (const float*)d_in[13];
    const float* fc2_b = (const float*)d_in[14];
    float* out = (float*)d_out;

    cudaFuncSetAttribute(xg_gemm, cudaFuncAttributeMaxDynamicSharedMemorySize, SMEM2_BYTES);
    cudaFuncSetAttribute(gru_rec, cudaFuncAttributeMaxDynamicSharedMemorySize, SMEMR_BYTES);

    xg_gemm<<<dim3(NCTA, Tn / TT), NTHR2, SMEM2_BYTES>>>(x, W_ih, b_ih);
    gru_rec<<<NCTA, NTHR, SMEMR_BYTES>>>(W_hh, b_hh, fc_w, fc_b);
    head_kernel<<<1, Bn>>>(g1, beta1, fc1_w, fc1_b, g2, beta2, fc2_w, fc2_b, out);
}

// round 3
// speedup vs baseline: 1.3028x; 1.3028x over previous
#include <cuda_runtime.h>
#include <math.h>

// Problem constants
#define Hn    81
#define G3    243          // 3*H
#define RPAD  244          // rows padded (243 real + 1 pad)
#define NPAIR 122
#define Fn    128
#define Tn    1024
#define Bn    512
#define BPC   4            // batches per CTA group
#define NCTA  128          // 512/4

// gemm config
#define GT     128         // gemm threads
#define RHALF  122         // rows per z-half
#define TT     64          // timesteps per gemm CTA
#define NITER  (TT/2)

// recurrence config
#define RT     256

// =====================================================================
// Device scratch: XG[t][ctab][r(244)] float4(4 batches) = 512 MB
// =====================================================================
__device__ float4 g_xg[Tn * NCTA * RPAD];
__device__ float g_h8[Bn * 8];

// ---------- packed f32x2 helpers ----------
static __device__ __forceinline__ unsigned long long dup2(float x) {
    unsigned long long r;
    asm("mov.b64 %0, {%1, %1};" : "=l"(r) : "f"(x));
    return r;
}
static __device__ __forceinline__ void ffma2(unsigned long long &d,
                                             unsigned long long a,
                                             unsigned long long b) {
    asm("fma.rn.f32x2 %0, %1, %2, %0;" : "+l"(d) : "l"(a), "l"(b));
}
static __device__ __forceinline__ unsigned long long addx2(unsigned long long a,
                                                           unsigned long long b) {
    unsigned long long r;
    asm("add.rn.f32x2 %0, %1, %2;" : "=l"(r) : "l"(a), "l"(b));
    return r;
}
static __device__ __forceinline__ float2 unpk(unsigned long long v) {
    float lo, hi;
    asm("mov.b64 {%0, %1}, %2;" : "=f"(lo), "=f"(hi) : "l"(v));
    return make_float2(lo, hi);
}

// ---------- fast activations (accurate: ex2-based) ----------
static __device__ __forceinline__ float sigm(float x) {
    x = fminf(fmaxf(x, -30.f), 30.f);
    return __fdividef(1.f, 1.f + __expf(-x));
}
static __device__ __forceinline__ float tanh_f(float x) {
    x = fminf(fmaxf(x, -20.f), 20.f);
    float e = __expf(-2.f * x);
    return __fdividef(1.f - e, 1.f + e);
}

// =====================================================================
// Kernel 1: XG = x @ W_ih^T + b_ih.
// grid (128 bgroups, 16 tchunks, 2 row-halves) x 128 threads.
// 3 CTAs/SM (70.6 KB smem) -> 3 warps/SMSP, fma-pipe-bound.
// Thread = 1 output row x 2 timesteps x 4 batches.
// =====================================================================
#define GSM_WS   (RHALF * Fn * 4)             // 62464
#define GSM_XS   (4 * Fn * 16)                // 8192: 4 bufs of float4[128]
#define GSM_BYTES (GSM_WS + GSM_XS)           // 70656

__global__ void __launch_bounds__(GT, 3) xg_gemm(
    const float* __restrict__ x,     // [B,1,T,F]
    const float* __restrict__ W_ih,  // [3H,F]
    const float* __restrict__ b_ih)  // [3H]
{
    extern __shared__ char sm[];
    float*  ws  = (float*)sm;                 // [k][rl] stride RHALF
    float4* xs4 = (float4*)(sm + GSM_WS);     // [buf(4)][f]

    const int tid   = threadIdx.x;
    const int ctab  = blockIdx.x;
    const int b0    = ctab * BPC;
    const int tbase = blockIdx.y * TT;
    const int z     = blockIdx.z;

    // load weight half (coalesced gmem read, strided STS)
    for (int idx = tid; idx < RHALF * Fn; idx += GT) {
        int k  = idx & (Fn - 1);
        int rl = idx >> 7;
        int r  = z * RHALF + rl;
        ws[k * RHALF + rl] = (r < G3) ? W_ih[r * Fn + k] : 0.f;
    }

    const int  rl  = tid;
    const int  rg  = z * RHALF + rl;
    const bool act = (rl < RHALF);
    const float bias = (act && rg < G3) ? b_ih[rg] : 0.f;

    // stage first t-pair (t = tbase, tbase+1); thread tid = feature f
    {
        const float* xb = x + (long)tbase * Fn + tid;
        long sb = (long)Tn * Fn;
        float4 a = make_float4(xb[(long)(b0+0)*sb], xb[(long)(b0+1)*sb],
                               xb[(long)(b0+2)*sb], xb[(long)(b0+3)*sb]);
        xb += Fn;
        float4 b = make_float4(xb[(long)(b0+0)*sb], xb[(long)(b0+1)*sb],
                               xb[(long)(b0+2)*sb], xb[(long)(b0+3)*sb]);
        xs4[0 * Fn + tid] = a;
        xs4[1 * Fn + tid] = b;
    }
    __syncthreads();

    for (int i = 0; i < NITER; i++) {
        const int cur = (i & 1) * 2;
        const int nxt = ((i + 1) & 1) * 2;

        // prefetch next t-pair into regs
        float4 qa, qb;
        const bool pf = (i + 1 < NITER);
        if (pf) {
            const float* xb = x + (long)(tbase + 2 * (i + 1)) * Fn + tid;
            long sb = (long)Tn * Fn;
            qa = make_float4(xb[(long)(b0+0)*sb], xb[(long)(b0+1)*sb],
                             xb[(long)(b0+2)*sb], xb[(long)(b0+3)*sb]);
            xb += Fn;
            qb = make_float4(xb[(long)(b0+0)*sb], xb[(long)(b0+1)*sb],
                             xb[(long)(b0+2)*sb], xb[(long)(b0+3)*sb]);
        }

        if (act) {
            unsigned long long c00 = 0, c01 = 0, c10 = 0, c11 = 0;
            const float* wp = ws + rl;
            const ulonglong2* x0 = (const ulonglong2*)(xs4 + (cur + 0) * Fn);
            const ulonglong2* x1 = (const ulonglong2*)(xs4 + (cur + 1) * Fn);
            #pragma unroll 8
            for (int k = 0; k < Fn; k++) {
                unsigned long long wd = dup2(wp[k * RHALF]);
                ulonglong2 a = x0[k];
                ulonglong2 b = x1[k];
                ffma2(c00, wd, a.x); ffma2(c01, wd, a.y);
                ffma2(c10, wd, b.x); ffma2(c11, wd, b.y);
            }
            const int t0 = tbase + 2 * i;
            float2 u0 = unpk(c00), u1 = unpk(c01), u2 = unpk(c10), u3 = unpk(c11);
            g_xg[((long)t0 * NCTA + ctab) * RPAD + rg] =
                make_float4(u0.x + bias, u0.y + bias, u1.x + bias, u1.y + bias);
            g_xg[((long)(t0 + 1) * NCTA + ctab) * RPAD + rg] =
                make_float4(u2.x + bias, u2.y + bias, u3.x + bias, u3.y + bias);
        }

        if (pf) {
            xs4[(nxt + 0) * Fn + tid] = qa;
            xs4[(nxt + 1) * Fn + tid] = qb;
        }
        __syncthreads();
    }
}

// =====================================================================
// Kernel 2: recurrence. 128 CTAs x 4 batches x 256 threads.
// W_hh lives in REGISTERS (zero weight-LDS traffic). Lane pairs (xor 1)
// split K=81: even lane ks 0..40, odd lane ks 41..80; shfl-reduce.
// =====================================================================
__global__ void __launch_bounds__(RT, 1) gru_rec(
    const float* __restrict__ W_hh,  // [3H,H]
    const float* __restrict__ b_hh,  // [3H]
    const float* __restrict__ fc_w,  // [8,H]
    const float* __restrict__ fc_b)  // [8]
{
    __shared__ float4 hs4[84];            // h state [j] (4 batches), j<81 used
    __shared__ float4 hg4[RPAD];          // hidden gates
    __shared__ float4 xgs[2 * RPAD];      // double-buffered xg tile

    const int tid  = threadIdx.x;
    const int lane = tid & 31;
    const int warp = tid >> 5;
    const int ctab = blockIdx.x;

    const int p     = warp * 16 + (lane >> 1);  // pair index, valid < 122
    const int kh    = lane & 1;
    const int kbase = kh * 41;                  // 0 or 41 (odd half has 40 ks)
    const int r0 = 2 * p, r1 = 2 * p + 1;

    // ---- W_hh slice -> registers (82 floats/thread) ----
    float wr0[41], wr1[41];
    #pragma unroll
    for (int i = 0; i < 41; i++) {
        int k = kbase + i;
        bool kok = (k < Hn);
        wr0[i] = (kok && r0 < G3) ? W_hh[r0 * Hn + k] : 0.f;
        wr1[i] = (kok && r1 < G3) ? W_hh[r1 * Hn + k] : 0.f;
    }
    const float bh0 = (r0 < G3) ? b_hh[r0] : 0.f;
    const float bh1 = (r1 < G3) ? b_hh[r1] : 0.f;

    // init h = 0 (incl. padding rows 81..83 read by padded k-iter), xg(t=0)
    if (tid < 84) hs4[tid] = make_float4(0.f, 0.f, 0.f, 0.f);
    if (tid < RPAD) xgs[tid] = g_xg[(long)ctab * RPAD + tid];
    __syncthreads();

    float* hs_f = (float*)hs4;

    for (int t = 0; t < Tn; t++) {
        const int cur = t & 1, nxt = cur ^ 1;

        // prefetch xg(t+1)
        float4 q = make_float4(0.f, 0.f, 0.f, 0.f);
        const bool pf = (t + 1 < Tn);
        if (pf && tid < RPAD)
            q = g_xg[((long)(t + 1) * NCTA + ctab) * RPAD + tid];

        // partial hg over this lane's k-half (weights from registers)
        unsigned long long c00 = 0, c01 = 0, c10 = 0, c11 = 0;
        const ulonglong2* hp = (const ulonglong2*)hs4;
        #pragma unroll
        for (int i = 0; i < 41; i++) {
            ulonglong2 hv = hp[kbase + i];
            unsigned long long w0 = dup2(wr0[i]);
            unsigned long long w1 = dup2(wr1[i]);
            ffma2(c00, w0, hv.x); ffma2(c01, w0, hv.y);
            ffma2(c10, w1, hv.x); ffma2(c11, w1, hv.y);
        }
        // lane-pair reduction (xor 1): both halves of K combined
        c00 = addx2(c00, __shfl_xor_sync(0xffffffffu, c00, 1));
        c01 = addx2(c01, __shfl_xor_sync(0xffffffffu, c01, 1));
        c10 = addx2(c10, __shfl_xor_sync(0xffffffffu, c10, 1));
        c11 = addx2(c11, __shfl_xor_sync(0xffffffffu, c11, 1));

        if (kh == 0 && p < NPAIR) {
            float2 u0 = unpk(c00), u1 = unpk(c01), u2 = unpk(c10), u3 = unpk(c11);
            hg4[r0] = make_float4(u0.x + bh0, u0.y + bh0, u1.x + bh0, u1.y + bh0);
            hg4[r1] = make_float4(u2.x + bh1, u2.y + bh1, u3.x + bh1, u3.y + bh1);
        }
        if (pf && tid < RPAD) xgs[nxt * RPAD + tid] = q;
        __syncthreads();

        // gate combine: 324 items over 256 threads
        const float* xgc = (const float*)(xgs + cur * RPAD);
        const float* hgf = (const float*)hg4;
        #pragma unroll
        for (int rep = 0; rep < 2; rep++) {
            int it = tid + rep * RT;
            if (it < Hn * 4) {
                float xr = xgc[it],       hr = hgf[it];
                float xz = xgc[324 + it], hz = hgf[324 + it];
                float xn = xgc[648 + it], hn = hgf[648 + it];
                float r = sigm(xr + hr);
                float z = sigm(xz + hz);
                float n = tanh_f(xn + r * hn);
                hs_f[it] = (1.f - z) * n + z * hs_f[it];
            }
        }
        __syncthreads();
    }

    // head stage 1: out8 = silu(h_last @ fc_w^T + fc_b)
    if (tid < 32) {
        int b = tid >> 3, f = tid & 7;
        float a = fc_b[f];
        #pragma unroll 27
        for (int j = 0; j < Hn; j++) a += hs_f[j * 4 + b] * fc_w[f * Hn + j];
        a = a * sigm(a);
        g_h8[(ctab * BPC + b) * 8 + f] = a;
    }
}

// =====================================================================
// Kernel 3: BN(8) -> fc1 -> silu -> BN(4) -> fc2. One CTA, 512 threads.
// =====================================================================
__global__ void __launch_bounds__(Bn) head_kernel(
    const float* __restrict__ g1, const float* __restrict__ beta1,
    const float* __restrict__ fc1_w, const float* __restrict__ fc1_b,
    const float* __restrict__ g2, const float* __restrict__ beta2,
    const float* __restrict__ fc2_w, const float* __restrict__ fc2_b,
    float* __restrict__ out)
{
    __shared__ float s8[Bn * 8];
    __shared__ float s4[Bn * 4];
    __shared__ float mu1[8], iv1[8], mu2[4], iv2[4];
    const int tid = threadIdx.x;

    for (int i = tid; i < Bn * 8; i += Bn) s8[i] = g_h8[i];
    __syncthreads();

    if (tid < 8) {
        float s = 0.f, ss = 0.f;
        for (int b = 0; b < Bn; b++) { float v = s8[b * 8 + tid]; s += v; ss += v * v; }
        float m = s * (1.f / Bn);
        float var = ss * (1.f / Bn) - m * m;   // biased variance
        mu1[tid] = m;
        iv1[tid] = rsqrtf(var + 1e-5f);
    }
    __syncthreads();

    {
        int b = tid;
        float y[8];
        #pragma unroll
        for (int f = 0; f < 8; f++)
            y[f] = (s8[b * 8 + f] - mu1[f]) * iv1[f] * g1[f] + beta1[f];
        #pragma unroll
        for (int o = 0; o < 4; o++) {
            float a = fc1_b[o];
            #pragma unroll
            for (int f = 0; f < 8; f++) a += y[f] * fc1_w[o * 8 + f];
            a = a * sigm(a);
            s4[b * 4 + o] = a;
        }
    }
    __syncthreads();

    if (tid < 4) {
        float s = 0.f, ss = 0.f;
        for (int b = 0; b < Bn; b++) { float v = s4[b * 4 + tid]; s += v; ss += v * v; }
        float m = s * (1.f / Bn);
        float var = ss * (1.f / Bn) - m * m;
        mu2[tid] = m;
        iv2[tid] = rsqrtf(var + 1e-5f);
    }
    __syncthreads();

    {
        int b = tid;
        float a = fc2_b[0];
        #pragma unroll
        for (int o = 0; o < 4; o++)
            a += ((s4[b * 4 + o] - mu2[o]) * iv2[o] * g2[o] + beta2[o]) * fc2_w[o];
        out[b] = a;
    }
}

// =====================================================================
extern "C" void kernel_launch(void* const* d_in, const int* in_sizes, int n_in,
                              void* d_out, int out_size) {
    const float* x     = (const float*)d_in[0];
    const float* W_ih  = (const float*)d_in[1];
    const float* W_hh  = (const float*)d_in[2];
    const float* b_ih  = (const float*)d_in[3];
    const float* b_hh  = (const float*)d_in[4];
    const float* fc_w  = (const float*)d_in[5];
    const float* fc_b  = (const float*)d_in[6];
    const float* g1    = (const float*)d_in[7];
    const float* beta1 = (const float*)d_in[8];
    const float* fc1_w = (const float*)d_in[9];
    const float* fc1_b = (const float*)d_in[10];
    const float* g2    = (const float*)d_in[11];
    const float* beta2 = (const float*)d_in[12];
    const float* fc2_w = (const float*)d_in[13];
    const float* fc2_b = (const float*)d_in[14];
    float* out = (float*)d_out;

    cudaFuncSetAttribute(xg_gemm, cudaFuncAttributeMaxDynamicSharedMemorySize, GSM_BYTES);

    xg_gemm<<<dim3(NCTA, Tn / TT, 2), GT, GSM_BYTES>>>(x, W_ih, b_ih);
    gru_rec<<<NCTA, RT>>>(W_hh, b_hh, fc_w, fc_b);
    head_kernel<<<1, Bn>>>(g1, beta1, fc1_w, fc1_b, g2, beta2, fc2_w, fc2_b, out);
}

// round 4
// speedup vs baseline: 1.4974x; 1.1494x over previous
#include <cuda_runtime.h>
#include <math.h>

// Problem constants
#define Hn    81
#define G3    243          // 3*H
#define RPAD  244
#define NPAIR 122
#define Fn    128
#define Tn    1024
#define Bn    512
#define BPC   4
#define NCTA  128          // 512/4

// ---- gemm v3 (register-tiled) config ----
#define GT3      256       // threads
#define PPAD     128       // padded row-pairs
#define WPITCH   260       // weight smem row pitch in floats (130 float2)
#define XCOLS    64        // cols per subtile = 16 t * 4 b
#define XPITCH   69        // x smem row pitch in floats (64 + 5 pad)
#define NSUB     8         // subtiles per CTA (128 t)
#define TSUB     16        // timesteps per subtile

#define GSM_W    (Fn * WPITCH * 4)            // 133120
#define GSM_X    (Fn * XPITCH * 4)            // 35328 per buffer
#define GSM3_BYTES (GSM_W + 2 * GSM_X)        // 203776 (~199 KB)

// recurrence config
#define RT     256

// =====================================================================
// Device scratch: XG[t][ctab][r(244)] float4(4 batches) = 512 MB
// =====================================================================
__device__ float4 g_xg[Tn * NCTA * RPAD];
__device__ float g_h8[Bn * 8];

// ---------- packed f32x2 helpers ----------
static __device__ __forceinline__ unsigned long long dup2(float x) {
    unsigned long long r;
    asm("mov.b64 %0, {%1, %1};" : "=l"(r) : "f"(x));
    return r;
}
static __device__ __forceinline__ void ffma2(unsigned long long &d,
                                             unsigned long long a,
                                             unsigned long long b) {
    asm("fma.rn.f32x2 %0, %1, %2, %0;" : "+l"(d) : "l"(a), "l"(b));
}
static __device__ __forceinline__ unsigned long long addx2(unsigned long long a,
                                                           unsigned long long b) {
    unsigned long long r;
    asm("add.rn.f32x2 %0, %1, %2;" : "=l"(r) : "l"(a), "l"(b));
    return r;
}
static __device__ __forceinline__ float2 unpk(unsigned long long v) {
    float lo, hi;
    asm("mov.b64 {%0, %1}, %2;" : "=f"(lo), "=f"(hi) : "l"(v));
    return make_float2(lo, hi);
}

// ---------- fast activations ----------
static __device__ __forceinline__ float sigm(float x) {
    x = fminf(fmaxf(x, -30.f), 30.f);
    return __fdividef(1.f, 1.f + __expf(-x));
}
static __device__ __forceinline__ float tanh_f(float x) {
    x = fminf(fmaxf(x, -20.f), 20.f);
    float e = __expf(-2.f * x);
    return __fdividef(1.f - e, 1.f + e);
}

// =====================================================================
// Kernel 1 (v3): XG = x @ W_ih^T + b_ih as a register-tiled GEMM.
// grid (128 ctab, 8 tchunk) x 256 threads. 1 CTA/SM.
// CTA: 128 row-pairs x (4 b x 128 t), 8 subtiles of 16 t.
// Thread: 4 row-pairs x 8 cols; weight pair rides in FFMA2 'a' operand.
// Per k per warp: 2 LDS.128 (w) + 8 scalar LDS (x) -> 10 wavefronts
// feeding 64 fma cycles: fma-bound.
// =====================================================================
__global__ void __launch_bounds__(GT3) xg_gemm3(
    const float* __restrict__ x,     // [B,1,T,F]
    const float* __restrict__ W_ih,  // [3H,F]
    const float* __restrict__ b_ih)  // [3H]
{
    extern __shared__ char sm[];
    float* wsm = (float*)sm;                        // [k][130 pairs] float2
    float* xsm = (float*)(sm + GSM_W);              // 2 buffers [k][XPITCH]

    const int tid  = threadIdx.x;
    const int tx   = tid & 7;        // col group
    const int ty   = tid >> 3;       // pair group (0..31) -> pairs ty*4..+3
    const int ctab = blockIdx.x;
    const int b0   = ctab * BPC;
    const int tch  = blockIdx.y * (NSUB * TSUB);    // CTA t-base

    // ---- zero weight smem (covers pad pairs), then stage W_ih^T ----
    for (int i = tid; i < Fn * WPITCH; i += GT3) wsm[i] = 0.f;
    __syncthreads();
    // W_ih[r][k] -> wsm[k*WPITCH + (r>>1)*2 + (r&1)]
    for (int idx = tid; idx < G3 * Fn; idx += GT3) {
        int k = idx & (Fn - 1);
        int r = idx >> 7;
        wsm[k * WPITCH + (r >> 1) * 2 + (r & 1)] = W_ih[r * Fn + k];
    }

    // per-thread biases for its 8 rows (4 pairs)
    float bi0[4], bi1[4];
    #pragma unroll
    for (int p = 0; p < 4; p++) {
        int P = ty * 4 + p;
        bi0[p] = (2 * P < G3)     ? b_ih[2 * P]     : 0.f;
        bi1[p] = (2 * P + 1 < G3) ? b_ih[2 * P + 1] : 0.f;
    }

    // ---- x loader mapping: k4 = lane-contiguous for coalesced LDG ----
    const int lk4 = tid & 31;        // float4 index along k (0..31)
    const int lc0 = tid >> 5;        // base col (0..7), cols lc0 + 8m
    const long sbt = (long)Tn * Fn;

    // stage subtile 0
    {
        const int t0 = tch;
        #pragma unroll
        for (int m = 0; m < 8; m++) {
            int c  = lc0 + 8 * m;
            int b  = c & 3, tl = c >> 2;
            const float4 v = *(const float4*)(x + (long)(b0 + b) * sbt
                                              + (long)(t0 + tl) * Fn + lk4 * 4);
            float* dst = xsm + c;                       // buffer 0
            dst[(lk4 * 4 + 0) * XPITCH] = v.x;
            dst[(lk4 * 4 + 1) * XPITCH] = v.y;
            dst[(lk4 * 4 + 2) * XPITCH] = v.z;
            dst[(lk4 * 4 + 3) * XPITCH] = v.w;
        }
    }
    __syncthreads();

    for (int s = 0; s < NSUB; s++) {
        const int cur = s & 1, nxt = cur ^ 1;
        const int t0 = tch + s * TSUB;

        // prefetch next subtile's x into registers
        float4 qv[8];
        const bool pf = (s + 1 < NSUB);
        if (pf) {
            const int tn0 = t0 + TSUB;
            #pragma unroll
            for (int m = 0; m < 8; m++) {
                int c = lc0 + 8 * m;
                int b = c & 3, tl = c >> 2;
                qv[m] = *(const float4*)(x + (long)(b0 + b) * sbt
                                         + (long)(tn0 + tl) * Fn + lk4 * 4);
            }
        }

        // ---- main compute: 4 pairs x 8 cols, K = 128 ----
        unsigned long long acc[4][8];
        #pragma unroll
        for (int p = 0; p < 4; p++)
            #pragma unroll
            for (int j = 0; j < 8; j++) acc[p][j] = 0ull;

        const float* xb = xsm + cur * (Fn * XPITCH) + tx;
        const float* wb = wsm + ty * 8;

        #pragma unroll 4
        for (int k = 0; k < Fn; k++) {
            const ulonglong2 w01 = *(const ulonglong2*)(wb + k * WPITCH);
            const ulonglong2 w23 = *(const ulonglong2*)(wb + k * WPITCH + 4);
            unsigned long long xd[8];
            #pragma unroll
            for (int j = 0; j < 8; j++) xd[j] = dup2(xb[k * XPITCH + 8 * j]);
            #pragma unroll
            for (int j = 0; j < 8; j++) {
                ffma2(acc[0][j], w01.x, xd[j]);
                ffma2(acc[1][j], w01.y, xd[j]);
                ffma2(acc[2][j], w23.x, xd[j]);
                ffma2(acc[3][j], w23.y, xd[j]);
            }
        }

        // ---- store results (+bias) ----
        {
            float* gout = (float*)g_xg;
            const int b  = tx & 3;
            const int ta = tx >> 2;
            #pragma unroll
            for (int p = 0; p < 4; p++) {
                int P = ty * 4 + p;
                if (P < NPAIR) {
                    int r0 = 2 * P;
                    #pragma unroll
                    for (int j = 0; j < 8; j++) {
                        int t = t0 + ta + 2 * j;
                        long base = ((long)t * NCTA + ctab) * RPAD;
                        float2 u = unpk(acc[p][j]);
                        gout[(base + r0) * 4 + b]     = u.x + bi0[p];
                        gout[(base + r0 + 1) * 4 + b] = u.y + bi1[p];
                    }
                }
            }
        }

        // write prefetched x into other buffer
        if (pf) {
            float* dst = xsm + nxt * (Fn * XPITCH) + lc0;
            #pragma unroll
            for (int m = 0; m < 8; m++) {
                float* d = dst + 8 * m;
                d[(lk4 * 4 + 0) * XPITCH] = qv[m].x;
                d[(lk4 * 4 + 1) * XPITCH] = qv[m].y;
                d[(lk4 * 4 + 2) * XPITCH] = qv[m].z;
                d[(lk4 * 4 + 3) * XPITCH] = qv[m].w;
            }
        }
        __syncthreads();
    }
}

// =====================================================================
// Kernel 2: recurrence (unchanged from R3). 128 CTAs x 256 threads.
// =====================================================================
__global__ void __launch_bounds__(RT, 1) gru_rec(
    const float* __restrict__ W_hh,  // [3H,H]
    const float* __restrict__ b_hh,  // [3H]
    const float* __restrict__ fc_w,  // [8,H]
    const float* __restrict__ fc_b)  // [8]
{
    __shared__ float4 hs4[84];
    __shared__ float4 hg4[RPAD];
    __shared__ float4 xgs[2 * RPAD];

    const int tid  = threadIdx.x;
    const int lane = tid & 31;
    const int warp = tid >> 5;
    const int ctab = blockIdx.x;

    const int p     = warp * 16 + (lane >> 1);
    const int kh    = lane & 1;
    const int kbase = kh * 41;
    const int r0 = 2 * p, r1 = 2 * p + 1;

    float wr0[41], wr1[41];
    #pragma unroll
    for (int i = 0; i < 41; i++) {
        int k = kbase + i;
        bool kok = (k < Hn);
        wr0[i] = (kok && r0 < G3) ? W_hh[r0 * Hn + k] : 0.f;
        wr1[i] = (kok && r1 < G3) ? W_hh[r1 * Hn + k] : 0.f;
    }
    const float bh0 = (r0 < G3) ? b_hh[r0] : 0.f;
    const float bh1 = (r1 < G3) ? b_hh[r1] : 0.f;

    if (tid < 84) hs4[tid] = make_float4(0.f, 0.f, 0.f, 0.f);
    if (tid < RPAD) xgs[tid] = g_xg[(long)ctab * RPAD + tid];
    __syncthreads();

    float* hs_f = (float*)hs4;

    for (int t = 0; t < Tn; t++) {
        const int cur = t & 1, nxt = cur ^ 1;

        float4 q = make_float4(0.f, 0.f, 0.f, 0.f);
        const bool pf = (t + 1 < Tn);
        if (pf && tid < RPAD)
            q = g_xg[((long)(t + 1) * NCTA + ctab) * RPAD + tid];

        unsigned long long c00 = 0, c01 = 0, c10 = 0, c11 = 0;
        const ulonglong2* hp = (const ulonglong2*)hs4;
        #pragma unroll
        for (int i = 0; i < 41; i++) {
            ulonglong2 hv = hp[kbase + i];
            unsigned long long w0 = dup2(wr0[i]);
            unsigned long long w1 = dup2(wr1[i]);
            ffma2(c00, w0, hv.x); ffma2(c01, w0, hv.y);
            ffma2(c10, w1, hv.x); ffma2(c11, w1, hv.y);
        }
        c00 = addx2(c00, __shfl_xor_sync(0xffffffffu, c00, 1));
        c01 = addx2(c01, __shfl_xor_sync(0xffffffffu, c01, 1));
        c10 = addx2(c10, __shfl_xor_sync(0xffffffffu, c10, 1));
        c11 = addx2(c11, __shfl_xor_sync(0xffffffffu, c11, 1));

        if (kh == 0 && p < NPAIR) {
            float2 u0 = unpk(c00), u1 = unpk(c01), u2 = unpk(c10), u3 = unpk(c11);
            hg4[r0] = make_float4(u0.x + bh0, u0.y + bh0, u1.x + bh0, u1.y + bh0);
            hg4[r1] = make_float4(u2.x + bh1, u2.y + bh1, u3.x + bh1, u3.y + bh1);
        }
        if (pf && tid < RPAD) xgs[nxt * RPAD + tid] = q;
        __syncthreads();

        const float* xgc = (const float*)(xgs + cur * RPAD);
        const float* hgf = (const float*)hg4;
        #pragma unroll
        for (int rep = 0; rep < 2; rep++) {
            int it = tid + rep * RT;
            if (it < Hn * 4) {
                float xr = xgc[it],       hr = hgf[it];
                float xz = xgc[324 + it], hz = hgf[324 + it];
                float xn = xgc[648 + it], hn = hgf[648 + it];
                float r = sigm(xr + hr);
                float z = sigm(xz + hz);
                float n = tanh_f(xn + r * hn);
                hs_f[it] = (1.f - z) * n + z * hs_f[it];
            }
        }
        __syncthreads();
    }

    if (tid < 32) {
        int b = tid >> 3, f = tid & 7;
        float a = fc_b[f];
        #pragma unroll 27
        for (int j = 0; j < Hn; j++) a += hs_f[j * 4 + b] * fc_w[f * Hn + j];
        a = a * sigm(a);
        g_h8[(ctab * BPC + b) * 8 + f] = a;
    }
}

// =====================================================================
// Kernel 3: BN(8) -> fc1 -> silu -> BN(4) -> fc2. One CTA, 512 threads.
// =====================================================================
__global__ void __launch_bounds__(Bn) head_kernel(
    const float* __restrict__ g1, const float* __restrict__ beta1,
    const float* __restrict__ fc1_w, const float* __restrict__ fc1_b,
    const float* __restrict__ g2, const float* __restrict__ beta2,
    const float* __restrict__ fc2_w, const float* __restrict__ fc2_b,
    float* __restrict__ out)
{
    __shared__ float s8[Bn * 8];
    __shared__ float s4[Bn * 4];
    __shared__ float mu1[8], iv1[8], mu2[4], iv2[4];
    const int tid = threadIdx.x;

    for (int i = tid; i < Bn * 8; i += Bn) s8[i] = g_h8[i];
    __syncthreads();

    if (tid < 8) {
        float s = 0.f, ss = 0.f;
        for (int b = 0; b < Bn; b++) { float v = s8[b * 8 + tid]; s += v; ss += v * v; }
        float m = s * (1.f / Bn);
        float var = ss * (1.f / Bn) - m * m;
        mu1[tid] = m;
        iv1[tid] = rsqrtf(var + 1e-5f);
    }
    __syncthreads();

    {
        int b = tid;
        float y[8];
        #pragma unroll
        for (int f = 0; f < 8; f++)
            y[f] = (s8[b * 8 + f] - mu1[f]) * iv1[f] * g1[f] + beta1[f];
        #pragma unroll
        for (int o = 0; o < 4; o++) {
            float a = fc1_b[o];
            #pragma unroll
            for (int f = 0; f < 8; f++) a += y[f] * fc1_w[o * 8 + f];
            a = a * sigm(a);
            s4[b * 4 + o] = a;
        }
    }
    __syncthreads();

    if (tid < 4) {
        float s = 0.f, ss = 0.f;
        for (int b = 0; b < Bn; b++) { float v = s4[b * 4 + tid]; s += v; ss += v * v; }
        float m = s * (1.f / Bn);
        float var = ss * (1.f / Bn) - m * m;
        mu2[tid] = m;
        iv2[tid] = rsqrtf(var + 1e-5f);
    }
    __syncthreads();

    {
        int b = tid;
        float a = fc2_b[0];
        #pragma unroll
        for (int o = 0; o < 4; o++)
            a += ((s4[b * 4 + o] - mu2[o]) * iv2[o] * g2[o] + beta2[o]) * fc2_w[o];
        out[b] = a;
    }
}

// =====================================================================
extern "C" void kernel_launch(void* const* d_in, const int* in_sizes, int n_in,
                              void* d_out, int out_size) {
    const float* x     = (const float*)d_in[0];
    const float* W_ih  = (const float*)d_in[1];
    const float* W_hh  = (const float*)d_in[2];
    const float* b_ih  = (const float*)d_in[3];
    const float* b_hh  = (const float*)d_in[4];
    const float* fc_w  = (const float*)d_in[5];
    const float* fc_b  = (const float*)d_in[6];
    const float* g1    = (const float*)d_in[7];
    const float* beta1 = (const float*)d_in[8];
    const float* fc1_w = (const float*)d_in[9];
    const float* fc1_b = (const float*)d_in[10];
    const float* g2    = (const float*)d_in[11];
    const float* beta2 = (const float*)d_in[12];
    const float* fc2_w = (const float*)d_in[13];
    const float* fc2_b = (const float*)d_in[14];
    float* out = (float*)d_out;

    cudaFuncSetAttribute(xg_gemm3, cudaFuncAttributeMaxDynamicSharedMemorySize, GSM3_BYTES);

    xg_gemm3<<<dim3(NCTA, Tn / (NSUB * TSUB)), GT3, GSM3_BYTES>>>(x, W_ih, b_ih);
    gru_rec<<<NCTA, RT>>>(W_hh, b_hh, fc_w, fc_b);
    head_kernel<<<1, Bn>>>(g1, beta1, fc1_w, fc1_b, g2, beta2, fc2_w, fc2_b, out);
}